// round 16
// baseline (speedup 1.0000x reference)
#include <cuda_runtime.h>

#define NN 50000
#define EE 1600000
#define FF 64
#define BETA 0.5f
#define NEG 0.2f

// ---------------- scratch (static device globals; no allocs) ----------------
__device__ int      g_is64;
__device__ int      g_src[EE];
__device__ int      g_dst[EE];
__device__ int      g_csr[EE];
__device__ int      g_rowptr[NN + 1];
__device__ int      g_fill[NN];
__device__ float    g_h[NN * FF];
__device__ float    g_as[NN];
__device__ float    g_ad[NN];
__device__ float    g_x1[NN * FF];
__device__ float    g_x2[NN * FF];
__device__ unsigned g_gmax[2];

// monotone float <-> uint encoding for atomicMax on floats (handles negatives)
__device__ __forceinline__ unsigned encf(float f) {
    unsigned u = __float_as_uint(f);
    return (u & 0x80000000u) ? ~u : (u | 0x80000000u);
}
__device__ __forceinline__ float decf(unsigned u) {
    unsigned b = (u & 0x80000000u) ? (u ^ 0x80000000u) : ~u;
    return __uint_as_float(b);
}

// ---------------- dtype detect: int64 edge_index has zero high words ----------------
__global__ void k_detect(const unsigned* __restrict__ e) {
    __shared__ int flag;
    if (threadIdx.x == 0) flag = 0;
    __syncthreads();
    unsigned v = 0;
    for (int i = threadIdx.x; i < 1024; i += 256) v |= e[2 * i + 1];
    if (v) atomicOr(&flag, 1);
    __syncthreads();
    if (threadIdx.x == 0) g_is64 = (flag == 0);
}

// convert edge_index (int64 or int32) -> int32 src/dst; also zero rowptr
__global__ void k_convert(const void* __restrict__ eidx) {
    int i = blockIdx.x * blockDim.x + threadIdx.x;
    if (i < 2 * EE) {
        int v;
        if (g_is64) v = (int)((const long long*)eidx)[i];
        else        v = ((const int*)eidx)[i];
        if (i < EE) g_src[i] = v;
        else        g_dst[i - EE] = v;
    }
    if (i <= NN) g_rowptr[i] = 0;
}

__global__ void k_hist() {
    int i = blockIdx.x * blockDim.x + threadIdx.x;
    if (i < EE) atomicAdd(&g_rowptr[g_dst[i] + 1], 1);
}

// single-block inclusive scan over rowptr[0..NN]; also init fill = row starts
__global__ void k_scan() {
    __shared__ int part[1024];
    const int T = 1024, M = NN + 1;
    const int chunk = (M + T - 1) / T;  // 49
    int t = threadIdx.x;
    int b0 = t * chunk;
    int b1 = min(b0 + chunk, M);
    int s = 0;
    for (int i = b0; i < b1; i++) s += g_rowptr[i];
    part[t] = s;
    __syncthreads();
    for (int off = 1; off < T; off <<= 1) {
        int v = (t >= off) ? part[t - off] : 0;
        __syncthreads();
        part[t] += v;
        __syncthreads();
    }
    int run = (t > 0) ? part[t - 1] : 0;
    for (int i = b0; i < b1; i++) {
        run += g_rowptr[i];
        g_rowptr[i] = run;
        if (i < NN) g_fill[i] = run;
    }
}

__global__ void k_scatter() {
    int i = blockIdx.x * blockDim.x + threadIdx.x;
    if (i < EE) {
        int d = g_dst[i];
        int pos = atomicAdd(&g_fill[d], 1);
        g_csr[pos] = g_src[i];
    }
}

__global__ void k_rst() { g_gmax[0] = 0u; g_gmax[1] = 0u; }

// ---------------- node GEMM: O = X @ Wm (+bias); EPI: as/ad + global max ----------------
template <bool EPI>
__global__ void __launch_bounds__(128)
k_gemm(const float* __restrict__ X, const float* __restrict__ Wm,
       const float* __restrict__ av, const float* __restrict__ bv,
       const float* __restrict__ bias, float* __restrict__ O)
{
    extern __shared__ float sm[];
    float* Ws = sm;                 // 4096
    float* Xs = sm + 4096;          // 128 * 65 (padded, conflict-free)
    float* As = Xs + 128 * 65;      // 64
    float* Bs = As + 64;            // 64
    int tid  = threadIdx.x;
    int row0 = blockIdx.x * 128;

    for (int i = tid; i < 1024; i += 128)
        ((float4*)Ws)[i] = ((const float4*)Wm)[i];
    if (EPI && tid < 64) { As[tid] = av[tid]; Bs[tid] = bv[tid]; }

    for (int i = tid; i < 2048; i += 128) {
        int r = i >> 4, c = i & 15;
        int grow = row0 + r;
        float4 v = make_float4(0.f, 0.f, 0.f, 0.f);
        if (grow < NN) v = ((const float4*)(X + (size_t)grow * FF))[c];
        float* d = &Xs[r * 65 + c * 4];
        d[0] = v.x; d[1] = v.y; d[2] = v.z; d[3] = v.w;
    }
    __syncthreads();

    int row = row0 + tid;
    float acc[64];
#pragma unroll
    for (int j = 0; j < 64; j++) acc[j] = 0.f;
    const float* xr = &Xs[tid * 65];
#pragma unroll 4
    for (int k = 0; k < 64; k++) {
        float xv = xr[k];
        const float4* wr = (const float4*)(Ws + k * 64);
#pragma unroll
        for (int j = 0; j < 16; j++) {
            float4 w = wr[j];
            acc[4 * j + 0] += xv * w.x;
            acc[4 * j + 1] += xv * w.y;
            acc[4 * j + 2] += xv * w.z;
            acc[4 * j + 3] += xv * w.w;
        }
    }

    float s = -3.4e38f, d2 = -3.4e38f;
    if (row < NN) {
        if (bias) {
#pragma unroll
            for (int j = 0; j < 64; j++) acc[j] += __ldg(&bias[j]);
        }
        float4* o = (float4*)(O + (size_t)row * FF);
#pragma unroll
        for (int j = 0; j < 16; j++)
            o[j] = make_float4(acc[4 * j], acc[4 * j + 1], acc[4 * j + 2], acc[4 * j + 3]);
        if (EPI) {
            s = 0.f; d2 = 0.f;
#pragma unroll
            for (int j = 0; j < 64; j++) { s += acc[j] * As[j]; d2 += acc[j] * Bs[j]; }
            g_as[row] = s;
            g_ad[row] = d2;
        }
    }
    if (EPI) {
        unsigned es = encf(s), ed = encf(d2);
#pragma unroll
        for (int off = 16; off; off >>= 1) {
            es = max(es, __shfl_xor_sync(0xFFFFFFFFu, es, off));
            ed = max(ed, __shfl_xor_sync(0xFFFFFFFFu, ed, off));
        }
        __shared__ unsigned ms[4], md[4];
        int w = tid >> 5;
        if ((tid & 31) == 0) { ms[w] = es; md[w] = ed; }
        __syncthreads();
        if (tid == 0) {
            unsigned a = max(max(ms[0], ms[1]), max(ms[2], ms[3]));
            unsigned c = max(max(md[0], md[1]), max(md[2], md[3]));
            atomicMax(&g_gmax[0], a);
            atomicMax(&g_gmax[1], c);
        }
    }
}

// ---------------- per-dst aggregation: softmax-weighted sum, no atomics ----------------
__global__ void __launch_bounds__(256)
k_agg(const float* __restrict__ x0, const float* __restrict__ bias,
      float* __restrict__ xout)
{
    int lane = threadIdx.x & 31;
    int dst  = (blockIdx.x * blockDim.x + threadIdx.x) >> 5;
    if (dst >= NN) return;

    int start = g_rowptr[dst];
    int end   = g_rowptr[dst + 1];
    float M = decf(g_gmax[0]) + decf(g_gmax[1]);
    M = (M >= 0.f) ? M : NEG * M;               // lrelu is monotone
    float add = g_ad[dst];

    float ax = 0.f, ay = 0.f, exsum = 0.f;
    const float* hb = g_h + lane * 2;

    for (int e0 = start; e0 < end; e0 += 32) {
        int e = e0 + lane;
        int s = 0; float ex = 0.f;
        if (e < end) {
            s = g_csr[e];
            float t = g_as[s] + add;
            t = (t >= 0.f) ? t : NEG * t;
            ex = __expf(t - M);
        }
        exsum += ex;
        int cnt = end - e0;
        if (cnt >= 32) {
#pragma unroll
            for (int j = 0; j < 32; j++) {
                int   sj  = __shfl_sync(0xFFFFFFFFu, s, j);
                float exj = __shfl_sync(0xFFFFFFFFu, ex, j);
                float2 hv = *(const float2*)(hb + sj * FF);
                ax += exj * hv.x;
                ay += exj * hv.y;
            }
        } else {
            for (int j = 0; j < cnt; j++) {
                int   sj  = __shfl_sync(0xFFFFFFFFu, s, j);
                float exj = __shfl_sync(0xFFFFFFFFu, ex, j);
                float2 hv = *(const float2*)(hb + sj * FF);
                ax += exj * hv.x;
                ay += exj * hv.y;
            }
        }
    }
#pragma unroll
    for (int off = 16; off; off >>= 1)
        exsum += __shfl_xor_sync(0xFFFFFFFFu, exsum, off);
    float r = (exsum > 0.f) ? (1.0f / exsum) : 0.f;

    float bx = __ldg(&bias[lane * 2]);
    float by = __ldg(&bias[lane * 2 + 1]);
    float2 xv = *(const float2*)(x0 + (size_t)dst * FF + lane * 2);
    float2 o;
    o.x = BETA * (ax * r + bx) + (1.f - BETA) * xv.x;
    o.y = BETA * (ay * r + by) + (1.f - BETA) * xv.y;
    *(float2*)(xout + (size_t)dst * FF + lane * 2) = o;
}

// ---------------- launch ----------------
extern "C" void kernel_launch(void* const* d_in, const int* in_sizes, int n_in,
                              void* d_out, int out_size)
{
    const float* x   = (const float*)d_in[0];
    const void*  eix = d_in[1];
    const float* W   = (const float*)d_in[2];
    const float* a_s = (const float*)d_in[3];
    const float* a_d = (const float*)d_in[4];
    const float* b   = (const float*)d_in[5];
    const float* fcw = (const float*)d_in[6];
    const float* fcb = (const float*)d_in[7];

    float* out = (float*)d_out;

    float *x1p, *x2p, *hp;
    cudaGetSymbolAddress((void**)&x1p, g_x1);
    cudaGetSymbolAddress((void**)&x2p, g_x2);
    cudaGetSymbolAddress((void**)&hp,  g_h);

    // output layout: (out, h) concatenated; fall back to scratch if h absent
    float* x3p = (out_size >= 2 * NN * FF) ? (out + (size_t)NN * FF) : x1p;

    const int smem = (4096 + 128 * 65 + 128) * (int)sizeof(float);  // 50176 B
    cudaFuncSetAttribute((const void*)k_gemm<true>,
                         cudaFuncAttributeMaxDynamicSharedMemorySize, smem);
    cudaFuncSetAttribute((const void*)k_gemm<false>,
                         cudaFuncAttributeMaxDynamicSharedMemorySize, smem);

    // ---- CSR build (once per launch; reused by all 3 layers) ----
    k_detect<<<1, 256>>>((const unsigned*)eix);
    k_convert<<<(2 * EE + 255) / 256, 256>>>(eix);
    k_hist<<<(EE + 255) / 256, 256>>>();
    k_scan<<<1, 1024>>>();
    k_scatter<<<(EE + 255) / 256, 256>>>();

    const int GB = (NN + 127) / 128;   // gemm blocks
    const int AB = (NN + 7) / 8;       // agg blocks (8 warps/block, 1 warp/dst)

    // layer 1: x -> x1
    k_rst<<<1, 1>>>();
    k_gemm<true><<<GB, 128, smem>>>(x, W, a_s, a_d, nullptr, hp);
    k_agg<<<AB, 256>>>(x, b, x1p);
    // layer 2: x1 -> x2 (residual vs original x)
    k_rst<<<1, 1>>>();
    k_gemm<true><<<GB, 128, smem>>>(x1p, W, a_s, a_d, nullptr, hp);
    k_agg<<<AB, 256>>>(x, b, x2p);
    // layer 3: x2 -> x3 (= h output)
    k_rst<<<1, 1>>>();
    k_gemm<true><<<GB, 128, smem>>>(x2p, W, a_s, a_d, nullptr, hp);
    k_agg<<<AB, 256>>>(x, b, x3p);
    // final FC: out = x3 @ fc_w + fc_b
    k_gemm<false><<<GB, 128, smem>>>(x3p, fcw, nullptr, nullptr, fcb, out);
}

// round 17
// speedup vs baseline: 1.0004x; 1.0004x over previous
#include <cuda_runtime.h>

#define NN 50000
#define EE 1600000
#define FF 64
#define BETA 0.5f
#define NEG 0.2f

// ---------------- scratch (static device globals; no allocs) ----------------
__device__ int      g_is64;
__device__ int      g_src[EE];
__device__ int      g_dst[EE];
__device__ int      g_csr[EE];
__device__ int      g_rowptr[NN + 1];
__device__ int      g_fill[NN];
__device__ float    g_h[NN * FF];
__device__ float    g_as[NN];
__device__ float    g_ad[NN];
__device__ float    g_x1[NN * FF];
__device__ float    g_x2[NN * FF];
__device__ unsigned g_gmax[2];

// monotone float <-> uint encoding for atomicMax on floats (handles negatives)
__device__ __forceinline__ unsigned encf(float f) {
    unsigned u = __float_as_uint(f);
    return (u & 0x80000000u) ? ~u : (u | 0x80000000u);
}
__device__ __forceinline__ float decf(unsigned u) {
    unsigned b = (u & 0x80000000u) ? (u ^ 0x80000000u) : ~u;
    return __uint_as_float(b);
}

// ---------------- dtype detect: int64 edge_index has zero high words ----------------
__global__ void k_detect(const unsigned* __restrict__ e) {
    __shared__ int flag;
    if (threadIdx.x == 0) flag = 0;
    __syncthreads();
    unsigned v = 0;
    for (int i = threadIdx.x; i < 1024; i += 256) v |= e[2 * i + 1];
    if (v) atomicOr(&flag, 1);
    __syncthreads();
    if (threadIdx.x == 0) g_is64 = (flag == 0);
}

// convert edge_index (int64 or int32) -> int32 src/dst; also zero rowptr
__global__ void k_convert(const void* __restrict__ eidx) {
    int i = blockIdx.x * blockDim.x + threadIdx.x;
    if (i < 2 * EE) {
        int v;
        if (g_is64) v = (int)((const long long*)eidx)[i];
        else        v = ((const int*)eidx)[i];
        if (i < EE) g_src[i] = v;
        else        g_dst[i - EE] = v;
    }
    if (i <= NN) g_rowptr[i] = 0;
}

__global__ void k_hist() {
    int i = blockIdx.x * blockDim.x + threadIdx.x;
    if (i < EE) atomicAdd(&g_rowptr[g_dst[i] + 1], 1);
}

// single-block inclusive scan over rowptr[0..NN]; also init fill = row starts
__global__ void k_scan() {
    __shared__ int part[1024];
    const int T = 1024, M = NN + 1;
    const int chunk = (M + T - 1) / T;  // 49
    int t = threadIdx.x;
    int b0 = t * chunk;
    int b1 = min(b0 + chunk, M);
    int s = 0;
    for (int i = b0; i < b1; i++) s += g_rowptr[i];
    part[t] = s;
    __syncthreads();
    for (int off = 1; off < T; off <<= 1) {
        int v = (t >= off) ? part[t - off] : 0;
        __syncthreads();
        part[t] += v;
        __syncthreads();
    }
    int run = (t > 0) ? part[t - 1] : 0;
    for (int i = b0; i < b1; i++) {
        run += g_rowptr[i];
        g_rowptr[i] = run;
        if (i < NN) g_fill[i] = run;
    }
}

__global__ void k_scatter() {
    int i = blockIdx.x * blockDim.x + threadIdx.x;
    if (i < EE) {
        int d = g_dst[i];
        int pos = atomicAdd(&g_fill[d], 1);
        g_csr[pos] = g_src[i];
    }
}

__global__ void k_rst() { g_gmax[0] = 0u; g_gmax[1] = 0u; }

// ---------------- node GEMM: O = X @ Wm (+bias); EPI: as/ad + global max ----------------
template <bool EPI>
__global__ void __launch_bounds__(128)
k_gemm(const float* __restrict__ X, const float* __restrict__ Wm,
       const float* __restrict__ av, const float* __restrict__ bv,
       const float* __restrict__ bias, float* __restrict__ O)
{
    extern __shared__ float sm[];
    float* Ws = sm;                 // 4096
    float* Xs = sm + 4096;          // 128 * 65 (padded, conflict-free)
    float* As = Xs + 128 * 65;      // 64
    float* Bs = As + 64;            // 64
    int tid  = threadIdx.x;
    int row0 = blockIdx.x * 128;

    for (int i = tid; i < 1024; i += 128)
        ((float4*)Ws)[i] = ((const float4*)Wm)[i];
    if (EPI && tid < 64) { As[tid] = av[tid]; Bs[tid] = bv[tid]; }

    for (int i = tid; i < 2048; i += 128) {
        int r = i >> 4, c = i & 15;
        int grow = row0 + r;
        float4 v = make_float4(0.f, 0.f, 0.f, 0.f);
        if (grow < NN) v = ((const float4*)(X + (size_t)grow * FF))[c];
        float* d = &Xs[r * 65 + c * 4];
        d[0] = v.x; d[1] = v.y; d[2] = v.z; d[3] = v.w;
    }
    __syncthreads();

    int row = row0 + tid;
    float acc[64];
#pragma unroll
    for (int j = 0; j < 64; j++) acc[j] = 0.f;
    const float* xr = &Xs[tid * 65];
#pragma unroll 4
    for (int k = 0; k < 64; k++) {
        float xv = xr[k];
        const float4* wr = (const float4*)(Ws + k * 64);
#pragma unroll
        for (int j = 0; j < 16; j++) {
            float4 w = wr[j];
            acc[4 * j + 0] += xv * w.x;
            acc[4 * j + 1] += xv * w.y;
            acc[4 * j + 2] += xv * w.z;
            acc[4 * j + 3] += xv * w.w;
        }
    }

    float s = -3.4e38f, d2 = -3.4e38f;
    if (row < NN) {
        if (bias) {
#pragma unroll
            for (int j = 0; j < 64; j++) acc[j] += __ldg(&bias[j]);
        }
        float4* o = (float4*)(O + (size_t)row * FF);
#pragma unroll
        for (int j = 0; j < 16; j++)
            o[j] = make_float4(acc[4 * j], acc[4 * j + 1], acc[4 * j + 2], acc[4 * j + 3]);
        if (EPI) {
            s = 0.f; d2 = 0.f;
#pragma unroll
            for (int j = 0; j < 64; j++) { s += acc[j] * As[j]; d2 += acc[j] * Bs[j]; }
            g_as[row] = s;
            g_ad[row] = d2;
        }
    }
    if (EPI) {
        unsigned es = encf(s), ed = encf(d2);
#pragma unroll
        for (int off = 16; off; off >>= 1) {
            es = max(es, __shfl_xor_sync(0xFFFFFFFFu, es, off));
            ed = max(ed, __shfl_xor_sync(0xFFFFFFFFu, ed, off));
        }
        __shared__ unsigned ms[4], md[4];
        int w = tid >> 5;
        if ((tid & 31) == 0) { ms[w] = es; md[w] = ed; }
        __syncthreads();
        if (tid == 0) {
            unsigned a = max(max(ms[0], ms[1]), max(ms[2], ms[3]));
            unsigned c = max(max(md[0], md[1]), max(md[2], md[3]));
            atomicMax(&g_gmax[0], a);
            atomicMax(&g_gmax[1], c);
        }
    }
}

// ---------------- per-dst aggregation: softmax-weighted sum, no atomics ----------------
__global__ void __launch_bounds__(256)
k_agg(const float* __restrict__ x0, const float* __restrict__ bias,
      float* __restrict__ xout)
{
    int lane = threadIdx.x & 31;
    int dst  = (blockIdx.x * blockDim.x + threadIdx.x) >> 5;
    if (dst >= NN) return;

    int start = g_rowptr[dst];
    int end   = g_rowptr[dst + 1];
    float M = decf(g_gmax[0]) + decf(g_gmax[1]);
    M = (M >= 0.f) ? M : NEG * M;               // lrelu is monotone
    float add = g_ad[dst];

    float ax = 0.f, ay = 0.f, exsum = 0.f;
    const float* hb = g_h + lane * 2;

    for (int e0 = start; e0 < end; e0 += 32) {
        int e = e0 + lane;
        int s = 0; float ex = 0.f;
        if (e < end) {
            s = g_csr[e];
            float t = g_as[s] + add;
            t = (t >= 0.f) ? t : NEG * t;
            ex = __expf(t - M);
        }
        exsum += ex;
        int cnt = end - e0;
        if (cnt >= 32) {
#pragma unroll
            for (int j = 0; j < 32; j++) {
                int   sj  = __shfl_sync(0xFFFFFFFFu, s, j);
                float exj = __shfl_sync(0xFFFFFFFFu, ex, j);
                float2 hv = *(const float2*)(hb + sj * FF);
                ax += exj * hv.x;
                ay += exj * hv.y;
            }
        } else {
            for (int j = 0; j < cnt; j++) {
                int   sj  = __shfl_sync(0xFFFFFFFFu, s, j);
                float exj = __shfl_sync(0xFFFFFFFFu, ex, j);
                float2 hv = *(const float2*)(hb + sj * FF);
                ax += exj * hv.x;
                ay += exj * hv.y;
            }
        }
    }
#pragma unroll
    for (int off = 16; off; off >>= 1)
        exsum += __shfl_xor_sync(0xFFFFFFFFu, exsum, off);
    float r = (exsum > 0.f) ? (1.0f / exsum) : 0.f;

    float bx = __ldg(&bias[lane * 2]);
    float by = __ldg(&bias[lane * 2 + 1]);
    float2 xv = *(const float2*)(x0 + (size_t)dst * FF + lane * 2);
    float2 o;
    o.x = BETA * (ax * r + bx) + (1.f - BETA) * xv.x;
    o.y = BETA * (ay * r + by) + (1.f - BETA) * xv.y;
    *(float2*)(xout + (size_t)dst * FF + lane * 2) = o;
}

// ---------------- launch ----------------
extern "C" void kernel_launch(void* const* d_in, const int* in_sizes, int n_in,
                              void* d_out, int out_size)
{
    const float* x   = (const float*)d_in[0];
    const void*  eix = d_in[1];
    const float* W   = (const float*)d_in[2];
    const float* a_s = (const float*)d_in[3];
    const float* a_d = (const float*)d_in[4];
    const float* b   = (const float*)d_in[5];
    const float* fcw = (const float*)d_in[6];
    const float* fcb = (const float*)d_in[7];

    float* out = (float*)d_out;

    float *x1p, *x2p, *hp;
    cudaGetSymbolAddress((void**)&x1p, g_x1);
    cudaGetSymbolAddress((void**)&x2p, g_x2);
    cudaGetSymbolAddress((void**)&hp,  g_h);

    // output layout: (out, h) concatenated; fall back to scratch if h absent
    float* x3p = (out_size >= 2 * NN * FF) ? (out + (size_t)NN * FF) : x1p;

    const int smem = (4096 + 128 * 65 + 128) * (int)sizeof(float);  // 50176 B
    cudaFuncSetAttribute((const void*)k_gemm<true>,
                         cudaFuncAttributeMaxDynamicSharedMemorySize, smem);
    cudaFuncSetAttribute((const void*)k_gemm<false>,
                         cudaFuncAttributeMaxDynamicSharedMemorySize, smem);

    // ---- CSR build (once per launch; reused by all 3 layers) ----
    k_detect<<<1, 256>>>((const unsigned*)eix);
    k_convert<<<(2 * EE + 255) / 256, 256>>>(eix);
    k_hist<<<(EE + 255) / 256, 256>>>();
    k_scan<<<1, 1024>>>();
    k_scatter<<<(EE + 255) / 256, 256>>>();

    const int GB = (NN + 127) / 128;   // gemm blocks
    const int AB = (NN + 7) / 8;       // agg blocks (8 warps/block, 1 warp/dst)

    // layer 1: x -> x1
    k_rst<<<1, 1>>>();
    k_gemm<true><<<GB, 128, smem>>>(x, W, a_s, a_d, nullptr, hp);
    k_agg<<<AB, 256>>>(x, b, x1p);
    // layer 2: x1 -> x2 (residual vs original x)
    k_rst<<<1, 1>>>();
    k_gemm<true><<<GB, 128, smem>>>(x1p, W, a_s, a_d, nullptr, hp);
    k_agg<<<AB, 256>>>(x, b, x2p);
    // layer 3: x2 -> x3 (= h output)
    k_rst<<<1, 1>>>();
    k_gemm<true><<<GB, 128, smem>>>(x2p, W, a_s, a_d, nullptr, hp);
    k_agg<<<AB, 256>>>(x, b, x3p);
    // final FC: out = x3 @ fc_w + fc_b
    k_gemm<false><<<GB, 128, smem>>>(x3p, fcw, nullptr, nullptr, fcb, out);
}